// round 1
// baseline (speedup 1.0000x reference)
#include <cuda_runtime.h>
#include <math.h>

#define T_STEPS 256
#define B_SZ    256
#define I_SZ    128
#define N_SZ    1024
#define O_SZ    64
#define M_ROWS  512   // stacked [x; y]

#define GRID_MAIN 128

__device__ float g_X   [M_ROWS * N_SZ];
__device__ float g_S0  [M_ROWS * N_SZ];
__device__ float g_S1  [M_ROWS * N_SZ];
__device__ float g_Ksum[M_ROWS * N_SZ];
__device__ float g_F0  [B_SZ * N_SZ];
__device__ float g_fc  [N_SZ];
__device__ unsigned g_bar_count = 0;
__device__ unsigned g_bar_phase = 0;

__constant__ float C_H     = 0.05f;
__constant__ float C_OMEGA = 6.283185307179586f;
__constant__ float C_GAMMA = 0.1f;
__constant__ float C_LAM   = 1.0f;
__constant__ float C_GAIN  = 0.03125f;  // 1/sqrt(1024)

// ---------------------------------------------------------------------------
// init: zero state + stage-0 GEMM input, precompute constant forcing tanh(b_ih)
// ---------------------------------------------------------------------------
__global__ void init_kernel(const float* __restrict__ b_ih) {
    int idx = blockIdx.x * blockDim.x + threadIdx.x;
    int stride = gridDim.x * blockDim.x;
    for (int i = idx; i < M_ROWS * N_SZ; i += stride) {
        g_X[i]  = 0.0f;
        g_S0[i] = 0.0f;
    }
    if (idx < N_SZ) g_fc[idx] = tanhf(b_ih[idx]);
}

// ---------------------------------------------------------------------------
// forcing at t=0: F0[b][n] = tanh(batch[0,b,:] . W_ih[n,:] + b_ih[n])
// ---------------------------------------------------------------------------
__global__ void forcing_kernel(const float* __restrict__ batch,
                               const float* __restrict__ W_ih,
                               const float* __restrict__ b_ih) {
    int idx = blockIdx.x * blockDim.x + threadIdx.x;  // 0 .. 256*1024-1
    int b = idx >> 10;
    int n = idx & (N_SZ - 1);
    const float4* xp = (const float4*)(batch + b * I_SZ);  // t = 0
    const float4* wp = (const float4*)(W_ih + n * I_SZ);
    float s = 0.0f;
#pragma unroll 8
    for (int i = 0; i < I_SZ / 4; ++i) {
        float4 x = __ldg(xp + i);
        float4 w = __ldg(wp + i);
        s += x.x * w.x + x.y * w.y + x.z * w.z + x.w * w.w;
    }
    g_F0[idx] = tanhf(s + __ldg(b_ih + n));
}

// ---------------------------------------------------------------------------
// grid barrier (self-resetting counter, monotonic phase => replay-safe)
// ---------------------------------------------------------------------------
__device__ __forceinline__ void grid_barrier(unsigned G) {
    __syncthreads();
    __threadfence();                       // publish this thread's writes (gpu scope)
    if (threadIdx.x == 0) {
        unsigned p = *(volatile unsigned*)&g_bar_phase;  // snapshot BEFORE arriving
        unsigned a = atomicAdd(&g_bar_count, 1u);
        if (a == G - 1u) {
            atomicExch(&g_bar_count, 0u);  // reset before release
            __threadfence();
            atomicAdd(&g_bar_phase, 1u);   // release
        } else {
            while (*(volatile unsigned*)&g_bar_phase == p) { /* spin */ }
        }
        __threadfence();                   // acquire
    }
    __syncthreads();
}

// ---------------------------------------------------------------------------
// tf32 helpers
// ---------------------------------------------------------------------------
__device__ __forceinline__ float f2tf32(float x) {
    float r;
    asm("cvt.rna.tf32.f32 %0, %1;" : "=f"(r) : "f"(x));
    return r;
}

__device__ __forceinline__ void mma_tf32(float* d, const float* a, const float* b) {
    const unsigned* A = (const unsigned*)a;
    const unsigned* B = (const unsigned*)b;
    asm volatile(
        "mma.sync.aligned.m16n8k8.row.col.f32.tf32.tf32.f32 "
        "{%0,%1,%2,%3},{%4,%5,%6,%7},{%8,%9},{%0,%1,%2,%3};"
        : "+f"(d[0]), "+f"(d[1]), "+f"(d[2]), "+f"(d[3])
        : "r"(A[0]), "r"(A[1]), "r"(A[2]), "r"(A[3]), "r"(B[0]), "r"(B[1]));
}

// ---------------------------------------------------------------------------
// main persistent kernel: 256 steps x 4 RK4 stages.
// Each stage: R = S_in @ W_hh^T  (512x1024 x 1024x1024), fused RK4 epilogue.
// 128 CTAs, each owns one 64x64 output tile (8 M-tiles x 16 N-tiles).
// ---------------------------------------------------------------------------
#define BK 32
#define SSTR 36   // smem row stride (floats): 16B-aligned float4 stores, conflict-free frags

__global__ void __launch_bounds__(256, 1)
main_kernel(const float* __restrict__ W_hh, const float* __restrict__ b_hh) {
    const int tid  = threadIdx.x;
    const int warp = tid >> 5;
    const int lane = tid & 31;
    const int wm   = warp >> 2;   // 0..1
    const int wn   = warp & 3;    // 0..3
    const int bm   = blockIdx.x >> 4;   // 0..7
    const int bn   = blockIdx.x & 15;   // 0..15
    const int M0   = bm * 64;
    const int N0   = bn * 64;
    const unsigned G = gridDim.x;

    __shared__ float As[64 * SSTR];
    __shared__ float Ws[64 * SSTR];

    // loader mapping: 2 float4 per thread per tile (64 rows x 8 float4/row)
    const int lr0 = tid >> 3;          // rows 0..31
    const int lr1 = lr0 + 32;          // rows 32..63
    const int lc  = (tid & 7) * 4;     // k offset within BK (floats)

    const float* wg0 = W_hh + (N0 + lr0) * N_SZ + lc;
    const float* wg1 = W_hh + (N0 + lr1) * N_SZ + lc;

    const bool is_x_half = (M0 < 256);
    const int  bb0 = M0 & 255;         // batch index base of this tile

    float* const bufs[2] = { g_S0, g_S1 };

    for (int t = 0; t < T_STEPS; ++t) {
        for (int s = 0; s < 4; ++s) {
            const float* Sin  = bufs[s & 1];
            float*       Sout = bufs[(s + 1) & 1];

            const float* ag0 = Sin + (M0 + lr0) * N_SZ + lc;
            const float* ag1 = Sin + (M0 + lr1) * N_SZ + lc;

            float acc[2][2][4];
#pragma unroll
            for (int i = 0; i < 2; ++i)
#pragma unroll
                for (int j = 0; j < 2; ++j)
#pragma unroll
                    for (int e = 0; e < 4; ++e) acc[i][j][e] = 0.0f;

            // prefetch k-chunk 0
            float4 pa0 = __ldcg((const float4*)(ag0));
            float4 pa1 = __ldcg((const float4*)(ag1));
            float4 pw0 = __ldg((const float4*)(wg0));
            float4 pw1 = __ldg((const float4*)(wg1));

            for (int it = 0; it < N_SZ / BK; ++it) {
                __syncthreads();  // previous chunk fully consumed
                // stage into smem (convert to tf32)
                float* a0p = &As[lr0 * SSTR + lc];
                a0p[0] = f2tf32(pa0.x); a0p[1] = f2tf32(pa0.y); a0p[2] = f2tf32(pa0.z); a0p[3] = f2tf32(pa0.w);
                float* a1p = &As[lr1 * SSTR + lc];
                a1p[0] = f2tf32(pa1.x); a1p[1] = f2tf32(pa1.y); a1p[2] = f2tf32(pa1.z); a1p[3] = f2tf32(pa1.w);
                float* w0p = &Ws[lr0 * SSTR + lc];
                w0p[0] = f2tf32(pw0.x); w0p[1] = f2tf32(pw0.y); w0p[2] = f2tf32(pw0.z); w0p[3] = f2tf32(pw0.w);
                float* w1p = &Ws[lr1 * SSTR + lc];
                w1p[0] = f2tf32(pw1.x); w1p[1] = f2tf32(pw1.y); w1p[2] = f2tf32(pw1.z); w1p[3] = f2tf32(pw1.w);
                __syncthreads();

                if (it + 1 < N_SZ / BK) {
                    int k0 = (it + 1) * BK;
                    pa0 = __ldcg((const float4*)(ag0 + k0));
                    pa1 = __ldcg((const float4*)(ag1 + k0));
                    pw0 = __ldg((const float4*)(wg0 + k0));
                    pw1 = __ldg((const float4*)(wg1 + k0));
                }

#pragma unroll
                for (int kk = 0; kk < BK; kk += 8) {
                    float af[2][4], bf[2][2];
#pragma unroll
                    for (int mt = 0; mt < 2; ++mt) {
                        int r = wm * 32 + mt * 16 + (lane >> 2);
                        int c = kk + (lane & 3);
                        af[mt][0] = As[r * SSTR + c];
                        af[mt][1] = As[(r + 8) * SSTR + c];
                        af[mt][2] = As[r * SSTR + c + 4];
                        af[mt][3] = As[(r + 8) * SSTR + c + 4];
                    }
#pragma unroll
                    for (int nt = 0; nt < 2; ++nt) {
                        int rn = wn * 16 + nt * 8 + (lane >> 2);
                        int c  = kk + (lane & 3);
                        bf[nt][0] = Ws[rn * SSTR + c];
                        bf[nt][1] = Ws[rn * SSTR + c + 4];
                    }
#pragma unroll
                    for (int mt = 0; mt < 2; ++mt)
#pragma unroll
                        for (int nt = 0; nt < 2; ++nt)
                            mma_tf32(acc[mt][nt], af[mt], bf[nt]);
                }
            }

            // ---------------- fused RK4-stage epilogue ----------------
            const float cmul = (s == 2) ? C_H : 0.5f * C_H;
#pragma unroll
            for (int mt = 0; mt < 2; ++mt) {
#pragma unroll
                for (int nt = 0; nt < 2; ++nt) {
#pragma unroll
                    for (int e = 0; e < 4; ++e) {
                        int row = M0 + wm * 32 + mt * 16 + (lane >> 2) + ((e & 2) ? 8 : 0);
                        int col = N0 + wn * 16 + nt * 8 + ((lane & 3) << 1) + (e & 1);
                        float r = acc[mt][nt][e];
                        int bb  = row & 255;
                        float sx = __ldcg(Sin + bb * N_SZ + col);
                        float sy = __ldcg(Sin + (bb + 256) * N_SZ + col);
                        float amp = C_LAM - (sx * sx + sy * sy);
                        float bh  = __ldg(b_hh + col);
                        float k;
                        if (is_x_half) {
                            float F = (t == 0) ? g_F0[bb * N_SZ + col] : g_fc[col];
                            k = amp * sx - C_OMEGA * sy + C_GAIN * (r + bh) + F - C_GAMMA * sx;
                        } else {
                            k = amp * sy + C_OMEGA * sx + C_GAIN * (r + bh) - C_GAMMA * sy;
                        }
                        int idx = row * N_SZ + col;
                        float xv = g_X[idx];
                        if (s == 0) {
                            g_Ksum[idx] = k;
                            Sout[idx] = xv + cmul * k;
                        } else if (s == 3) {
                            float xn = xv + (C_H / 6.0f) * (g_Ksum[idx] + k);
                            g_X[idx]  = xn;
                            Sout[idx] = xn;
                        } else {
                            g_Ksum[idx] += 2.0f * k;
                            Sout[idx] = xv + cmul * k;
                        }
                    }
                }
            }
            grid_barrier(G);
        }
    }
}

// ---------------------------------------------------------------------------
// output: out[b][o] = x_T[b,:] . W_ho[o,:] + b_ho[o]
// ---------------------------------------------------------------------------
__global__ void out_kernel(const float* __restrict__ W_ho,
                           const float* __restrict__ b_ho,
                           float* __restrict__ out) {
    int b   = blockIdx.x;
    int tid = threadIdx.x;
    int o   = tid >> 2;
    int q   = tid & 3;
    const float4* xp = (const float4*)(g_X + b * N_SZ + q * 256);
    const float4* wp = (const float4*)(W_ho + o * N_SZ + q * 256);
    float s = 0.0f;
#pragma unroll 8
    for (int i = 0; i < 64; ++i) {
        float4 x = xp[i];
        float4 w = __ldg(wp + i);
        s += x.x * w.x + x.y * w.y + x.z * w.z + x.w * w.w;
    }
    s += __shfl_xor_sync(0xffffffffu, s, 1);
    s += __shfl_xor_sync(0xffffffffu, s, 2);
    if (q == 0) out[b * O_SZ + o] = s + __ldg(b_ho + o);
}

// ---------------------------------------------------------------------------
extern "C" void kernel_launch(void* const* d_in, const int* in_sizes, int n_in,
                              void* d_out, int out_size) {
    const float* batch = (const float*)d_in[0];
    const float* W_ih  = (const float*)d_in[1];
    const float* b_ih  = (const float*)d_in[2];
    const float* W_hh  = (const float*)d_in[3];
    const float* b_hh  = (const float*)d_in[4];
    const float* W_ho  = (const float*)d_in[5];
    const float* b_ho  = (const float*)d_in[6];
    float* out = (float*)d_out;

    init_kernel<<<512, 256>>>(b_ih);
    forcing_kernel<<<(B_SZ * N_SZ) / 256, 256>>>(batch, W_ih, b_ih);
    main_kernel<<<GRID_MAIN, 256>>>(W_hh, b_hh);
    out_kernel<<<B_SZ, 256>>>(W_ho, b_ho, out);
}

// round 2
// speedup vs baseline: 1.5961x; 1.5961x over previous
#include <cuda_runtime.h>
#include <math.h>

#define T_STEPS 256
#define B_SZ    256
#define I_SZ    128
#define N_SZ    1024
#define O_SZ    64
#define M_ROWS  512   // stacked [x; y]

#define GRID_MAIN 128
#define BM 128
#define BN 32
#define BK 32
#define WSTR 1036     // 1024 + 12 pad -> conflict-free B-frag LDS
#define ASTR 36       // 32 + 4 pad   -> conflict-free A-frag LDS
#define LSTR 33       // local state arrays

// dynamic smem layout (floats):
//   Wsm  [32][WSTR]      33152
//   Asm  [2][128][ASTR]   9216
//   Sloc [128][LSTR]      4224
//   Xs   [128][LSTR]      4224
//   Ks   [128][LSTR]      4224
//   fcs[32], bhs[32]        64
#define SMEM_FLOATS (32*WSTR + 2*128*ASTR + 3*128*LSTR + 64)
#define SMEM_BYTES  (SMEM_FLOATS * 4)

__device__ float g_X [M_ROWS * N_SZ];
__device__ float g_S0[M_ROWS * N_SZ];
__device__ float g_S1[M_ROWS * N_SZ];
__device__ float g_F0[B_SZ * N_SZ];
__device__ float g_fc[N_SZ];
__device__ unsigned g_bar_count = 0;
__device__ unsigned g_bar_phase = 0;

__constant__ float C_H     = 0.05f;
__constant__ float C_OMEGA = 6.283185307179586f;
__constant__ float C_GAMMA = 0.1f;
__constant__ float C_LAM   = 1.0f;
__constant__ float C_GAIN  = 0.03125f;  // 1/sqrt(1024)

// ---------------------------------------------------------------------------
__global__ void init_kernel(const float* __restrict__ b_ih) {
    int idx = blockIdx.x * blockDim.x + threadIdx.x;
    int stride = gridDim.x * blockDim.x;
    for (int i = idx; i < M_ROWS * N_SZ; i += stride) g_S0[i] = 0.0f;
    if (idx < N_SZ) g_fc[idx] = tanhf(b_ih[idx]);
}

// ---------------------------------------------------------------------------
__global__ void forcing_kernel(const float* __restrict__ batch,
                               const float* __restrict__ W_ih,
                               const float* __restrict__ b_ih) {
    int idx = blockIdx.x * blockDim.x + threadIdx.x;
    int b = idx >> 10;
    int n = idx & (N_SZ - 1);
    const float4* xp = (const float4*)(batch + b * I_SZ);
    const float4* wp = (const float4*)(W_ih + n * I_SZ);
    float s = 0.0f;
#pragma unroll 8
    for (int i = 0; i < I_SZ / 4; ++i) {
        float4 x = __ldg(xp + i);
        float4 w = __ldg(wp + i);
        s += x.x * w.x + x.y * w.y + x.z * w.z + x.w * w.w;
    }
    g_F0[idx] = tanhf(s + __ldg(b_ih + n));
}

// ---------------------------------------------------------------------------
__device__ __forceinline__ void grid_barrier(unsigned G) {
    __syncthreads();
    __threadfence();                       // publish (gpu scope)
    if (threadIdx.x == 0) {
        unsigned p = *(volatile unsigned*)&g_bar_phase;
        unsigned a = atomicAdd(&g_bar_count, 1u);
        if (a == G - 1u) {
            atomicExch(&g_bar_count, 0u);
            __threadfence();
            atomicAdd(&g_bar_phase, 1u);
        } else {
            while (*(volatile unsigned*)&g_bar_phase == p) { }
        }
        __threadfence();                   // acquire
    }
    __syncthreads();
}

// ---------------------------------------------------------------------------
__device__ __forceinline__ float f2tf32(float x) {
    float r;
    asm("cvt.rna.tf32.f32 %0, %1;" : "=f"(r) : "f"(x));
    return r;
}

__device__ __forceinline__ void mma_tf32(float* d, const float* a, const float* b) {
    const unsigned* A = (const unsigned*)a;
    const unsigned* B = (const unsigned*)b;
    asm volatile(
        "mma.sync.aligned.m16n8k8.row.col.f32.tf32.tf32.f32 "
        "{%0,%1,%2,%3},{%4,%5,%6,%7},{%8,%9},{%0,%1,%2,%3};"
        : "+f"(d[0]), "+f"(d[1]), "+f"(d[2]), "+f"(d[3])
        : "r"(A[0]), "r"(A[1]), "r"(A[2]), "r"(A[3]), "r"(B[0]), "r"(B[1]));
}

// ---------------------------------------------------------------------------
// main persistent kernel.
// Grid 128 = 4 m-tiles (64 batches, x+y rows => 128 A-rows) x 32 n-tiles (32 cols).
// W n-slice resident in SMEM (tf32). A streamed from global, double-buffered.
// Epilogue fully local: X, Ksum, own-column Sin all in per-CTA SMEM.
// ---------------------------------------------------------------------------
__global__ void __launch_bounds__(256, 1)
main_kernel(const float* __restrict__ W_hh, const float* __restrict__ b_hh) {
    extern __shared__ float sm[];
    float* Wsm  = sm;
    float* Asm  = Wsm + 32 * WSTR;
    float* Sloc = Asm + 2 * 128 * ASTR;
    float* Xs   = Sloc + 128 * LSTR;
    float* Ks   = Xs + 128 * LSTR;
    float* fcs  = Ks + 128 * LSTR;
    float* bhs  = fcs + 32;

    const int tid  = threadIdx.x;
    const int lane = tid & 31;
    const int wm   = tid >> 5;           // warp 0..7 -> 16-row strip
    const int bn   = blockIdx.x & 31;
    const int bm   = blockIdx.x >> 5;
    const int N0   = bn * BN;
    const int batch0 = bm * 64;
    const unsigned G = gridDim.x;
    const bool isx = (wm < 4);

    // ---- one-time: W slice -> smem (tf32), local state zero, fc/bhh slices ----
    for (int i = tid; i < 32 * 256; i += 256) {
        int r = i >> 8, c4 = (i & 255) * 4;
        float4 w = __ldg((const float4*)(W_hh + (N0 + r) * N_SZ + c4));
        float* p = &Wsm[r * WSTR + c4];
        p[0] = f2tf32(w.x); p[1] = f2tf32(w.y); p[2] = f2tf32(w.z); p[3] = f2tf32(w.w);
    }
    for (int i = tid; i < 128 * LSTR; i += 256) { Sloc[i] = 0.0f; Xs[i] = 0.0f; Ks[i] = 0.0f; }
    if (tid < 32) { fcs[tid] = g_fc[N0 + tid]; bhs[tid] = __ldg(b_hh + N0 + tid); }
    __syncthreads();

    // ---- A loader mapping: 4 float4 per thread per chunk ----
    int arow[4], gofs[4];
    const int c4 = (tid & 7) * 4;
    for (int i = 0; i < 4; ++i) {
        arow[i] = i * 32 + (tid >> 3);
        int grow = batch0 + arow[i] + (arow[i] >= 64 ? 192 : 0);
        gofs[i] = grow * N_SZ + c4;
    }

    float* const bufs[2] = { g_S0, g_S1 };

    for (int t = 0; t < T_STEPS; ++t) {
        for (int s = 0; s < 4; ++s) {
            const float* Sin = bufs[s & 1];
            float*       Sout = bufs[(s + 1) & 1];

            float acc[4][4];
#pragma unroll
            for (int i = 0; i < 4; ++i)
#pragma unroll
                for (int j = 0; j < 4; ++j) acc[i][j] = 0.0f;

            float4 pa[4], pn[4];
#pragma unroll
            for (int i = 0; i < 4; ++i)
                pa[i] = __ldcg((const float4*)(Sin + gofs[i]));

            for (int it = 0; it < N_SZ / BK; ++it) {
                if (it + 1 < N_SZ / BK) {
#pragma unroll
                    for (int i = 0; i < 4; ++i)
                        pn[i] = __ldcg((const float4*)(Sin + gofs[i] + (it + 1) * BK));
                }
                float* Ab = Asm + (it & 1) * 128 * ASTR;
#pragma unroll
                for (int i = 0; i < 4; ++i) {
                    float* p = &Ab[arow[i] * ASTR + c4];
                    p[0] = f2tf32(pa[i].x); p[1] = f2tf32(pa[i].y);
                    p[2] = f2tf32(pa[i].z); p[3] = f2tf32(pa[i].w);
                }
                __syncthreads();

                const int kb = it * BK;
#pragma unroll
                for (int kk = 0; kk < BK; kk += 8) {
                    float af[4];
                    const int rA = wm * 16 + (lane >> 2);
                    const int cA = kk + (lane & 3);
                    af[0] = Ab[rA * ASTR + cA];
                    af[1] = Ab[(rA + 8) * ASTR + cA];
                    af[2] = Ab[rA * ASTR + cA + 4];
                    af[3] = Ab[(rA + 8) * ASTR + cA + 4];
#pragma unroll
                    for (int nt = 0; nt < 4; ++nt) {
                        const int rB = nt * 8 + (lane >> 2);
                        const int cB = kb + kk + (lane & 3);
                        float bf[2];
                        bf[0] = Wsm[rB * WSTR + cB];
                        bf[1] = Wsm[rB * WSTR + cB + 4];
                        mma_tf32(acc[nt], af, bf);
                    }
                }
#pragma unroll
                for (int i = 0; i < 4; ++i) pa[i] = pn[i];
            }

            // ---------------- fused RK4-stage epilogue (all local) ----------------
            const float cmul = (s == 2) ? C_H : 0.5f * C_H;
            const int r0 = wm * 16 + (lane >> 2);
            float kv[4][4];
            // phase A: read Sin from Sloc, compute stage derivative k
#pragma unroll
            for (int nt = 0; nt < 4; ++nt) {
#pragma unroll
                for (int e = 0; e < 4; ++e) {
                    const int rl = r0 + 8 * (e >> 1);
                    const int cl = nt * 8 + 2 * (lane & 3) + (e & 1);
                    const int rx = isx ? rl : rl - 64;
                    const float sx = Sloc[rx * LSTR + cl];
                    const float sy = Sloc[(rx + 64) * LSTR + cl];
                    const float amp = C_LAM - (sx * sx + sy * sy);
                    const float rr = acc[nt][e];
                    float k;
                    if (isx) {
                        float F = (t == 0) ? g_F0[(batch0 + rx) * N_SZ + N0 + cl] : fcs[cl];
                        k = amp * sx - C_OMEGA * sy + C_GAIN * (rr + bhs[cl]) + F - C_GAMMA * sx;
                    } else {
                        k = amp * sy + C_OMEGA * sx + C_GAIN * (rr + bhs[cl]) - C_GAMMA * sy;
                    }
                    kv[nt][e] = k;
                }
            }
            __syncthreads();  // all Sloc reads done before overwrites
            // phase B: update Ksum/X, write Sloc + global Sout
#pragma unroll
            for (int nt = 0; nt < 4; ++nt) {
#pragma unroll
                for (int eh = 0; eh < 2; ++eh) {
                    const int rl  = r0 + 8 * eh;
                    const int cl0 = nt * 8 + 2 * (lane & 3);
                    float2 so;
#pragma unroll
                    for (int j = 0; j < 2; ++j) {
                        const int il = rl * LSTR + cl0 + j;
                        const float k = kv[nt][eh * 2 + j];
                        const float xv = Xs[il];
                        float sv;
                        if (s == 0)      { Ks[il] = k;                    sv = xv + cmul * k; }
                        else if (s == 3) { float xn = xv + (C_H / 6.0f) * (Ks[il] + k);
                                           Xs[il] = xn;                   sv = xn; }
                        else             { Ks[il] += 2.0f * k;            sv = xv + cmul * k; }
                        (j == 0 ? so.x : so.y) = sv;
                        Sloc[il] = sv;
                    }
                    const int grow = batch0 + rl + (isx ? 0 : 192);
                    const int gi = grow * N_SZ + N0 + cl0;
                    *(float2*)(Sout + gi) = so;
                    if (t == T_STEPS - 1 && s == 3) *(float2*)(g_X + gi) = so;
                }
            }
            grid_barrier(G);
        }
    }
}

// ---------------------------------------------------------------------------
__global__ void out_kernel(const float* __restrict__ W_ho,
                           const float* __restrict__ b_ho,
                           float* __restrict__ out) {
    int b   = blockIdx.x;
    int tid = threadIdx.x;
    int o   = tid >> 2;
    int q   = tid & 3;
    const float4* xp = (const float4*)(g_X + b * N_SZ + q * 256);
    const float4* wp = (const float4*)(W_ho + o * N_SZ + q * 256);
    float s = 0.0f;
#pragma unroll 8
    for (int i = 0; i < 64; ++i) {
        float4 x = xp[i];
        float4 w = __ldg(wp + i);
        s += x.x * w.x + x.y * w.y + x.z * w.z + x.w * w.w;
    }
    s += __shfl_xor_sync(0xffffffffu, s, 1);
    s += __shfl_xor_sync(0xffffffffu, s, 2);
    if (q == 0) out[b * O_SZ + o] = s + __ldg(b_ho + o);
}

// ---------------------------------------------------------------------------
extern "C" void kernel_launch(void* const* d_in, const int* in_sizes, int n_in,
                              void* d_out, int out_size) {
    const float* batch = (const float*)d_in[0];
    const float* W_ih  = (const float*)d_in[1];
    const float* b_ih  = (const float*)d_in[2];
    const float* W_hh  = (const float*)d_in[3];
    const float* b_hh  = (const float*)d_in[4];
    const float* W_ho  = (const float*)d_in[5];
    const float* b_ho  = (const float*)d_in[6];
    float* out = (float*)d_out;

    cudaFuncSetAttribute(main_kernel,
                         cudaFuncAttributeMaxDynamicSharedMemorySize, SMEM_BYTES);

    init_kernel<<<512, 256>>>(b_ih);
    forcing_kernel<<<(B_SZ * N_SZ) / 256, 256>>>(batch, W_ih, b_ih);
    main_kernel<<<GRID_MAIN, 256, SMEM_BYTES>>>(W_hh, b_hh);
    out_kernel<<<B_SZ, 256>>>(W_ho, b_ho, out);
}